// round 7
// baseline (speedup 1.0000x reference)
#include <cuda_runtime.h>
#include <cuda_fp16.h>
#include <mma.h>
#include <math.h>
#include <stdint.h>

using namespace nvcuda;

#define BATCH 2
#define SEQ   2048
#define HID   4096
#define NHEAD 32
#define HDIM  128
#define MROWS (BATCH*SEQ)     /* 4096 */
#define QKVN  (3*HID)         /* 12288 */

// ---------------- scratch ----------------
__device__ __half g_Xhi   [MROWS*HID];
__device__ __half g_Xlo   [MROWS*HID];
__device__ __half g_Wqkvhi[QKVN*HID];
__device__ __half g_Wqkvlo[QKVN*HID];
__device__ __half g_Wohi  [HID*HID];
__device__ __half g_Wolo  [HID*HID];
__device__ __half g_Qhi   [MROWS*HID];
__device__ __half g_Qlo   [MROWS*HID];
__device__ __half g_Khi   [MROWS*HID];
__device__ __half g_Klo   [MROWS*HID];
__device__ __half g_V     [MROWS*HID];
__device__ __half g_AOhi  [MROWS*HID];
__device__ __half g_AOlo  [MROWS*HID];
__device__ float  g_cos   [SEQ*64];
__device__ float  g_sin   [SEQ*64];

__device__ __forceinline__ void splitf(float x, __half &hi, __half &lo) {
    hi = __float2half(x);
    lo = __float2half(x - __half2float(hi));
}

// ---------------- cp.async helpers ----------------
static __device__ __forceinline__ uint32_t smem_u32(const void* p) {
    uint32_t a;
    asm("{ .reg .u64 t; cvta.to.shared.u64 t, %1; cvt.u32.u64 %0, t; }" : "=r"(a) : "l"(p));
    return a;
}
static __device__ __forceinline__ void cp_async16(uint32_t dst, const void* src) {
    asm volatile("cp.async.cg.shared.global [%0], [%1], 16;\n" :: "r"(dst), "l"(src));
}
#define CP_COMMIT() asm volatile("cp.async.commit_group;\n" ::: "memory")
#define CP_WAIT1()  asm volatile("cp.async.wait_group 1;\n" ::: "memory")

// ---------------- elementwise split kernels ----------------
__device__ __forceinline__ void split_body(const float* __restrict__ src,
                                           __half* __restrict__ hi,
                                           __half* __restrict__ lo, int n) {
    int idx = blockIdx.x * blockDim.x + threadIdx.x;
    if (idx < n) {
        float x = src[idx];
        __half h, l; splitf(x, h, l);
        hi[idx] = h; lo[idx] = l;
    }
}
__global__ void __launch_bounds__(256) split_x_kernel(const float* __restrict__ src) {
    split_body(src, g_Xhi, g_Xlo, MROWS*HID);
}
__global__ void __launch_bounds__(256) split_wqkv_kernel(const float* __restrict__ src) {
    split_body(src, g_Wqkvhi, g_Wqkvlo, QKVN*HID);
}
__global__ void __launch_bounds__(256) split_wo_kernel(const float* __restrict__ src) {
    split_body(src, g_Wohi, g_Wolo, HID*HID);
}

// ---------------- RoPE cos/sin table ----------------
__global__ void __launch_bounds__(256) rope_table_kernel() {
    int idx = blockIdx.x * blockDim.x + threadIdx.x;
    if (idx >= SEQ*64) return;
    int i = idx & 63;
    int s = idx >> 6;
    double inv = pow(10000.0, -((double)(2*i)) / 128.0);
    float invf = (float)inv;
    float ang  = (float)s * invf;
    g_cos[idx] = (float)cos((double)ang);
    g_sin[idx] = (float)sin((double)ang);
}

// =====================================================================
//  Pipelined split-fp16 GEMM: CTA 128x128, 256 threads, warp 64x32.
//  KC=32, 2-stage cp.async, 2 CTAs/SM (cross-CTA bubble hiding).
//  TERMS: 3 or 2 split terms.
//  EPI: 0 = fp32 C direct ; 1 = fused RoPE+transpose+split (Q/K) ;
//       2 = direct fp16 V transpose.
// =====================================================================

#define KC        32
#define ARR_HALF  (128*40)                 /* 32 data halves + 8 pad */
#define STAGE_HALF (4*ARR_HALF)            /* 20480 */
#define STAGE_BYTES (STAGE_HALF*2)         /* 40960 */
#define GEMM_SMEM (2*STAGE_BYTES)          /* 81920 -> 2 CTAs/SM */

static __device__ __forceinline__ void gemm4_load_stage(
    uint32_t stage_base, int tid,
    const __half* __restrict__ Ahi, const __half* __restrict__ Alo,
    const __half* __restrict__ Bhi, const __half* __restrict__ Blo,
    int bm, int bn, int K, int k0)
{
    int chunk = tid & 3;        // 16B chunk within 64B data row
    int r0    = tid >> 2;       // 0..63
    const char* gAh = (const char*)(Ahi + (size_t)bm * K + k0) + chunk * 16;
    const char* gAl = (const char*)(Alo + (size_t)bm * K + k0) + chunk * 16;
    const char* gBh = (const char*)(Bhi + (size_t)bn * K + k0) + chunk * 16;
    const char* gBl = (const char*)(Blo + (size_t)bn * K + k0) + chunk * 16;
    #pragma unroll
    for (int u = 0; u < 2; u++) {
        int row = r0 + u * 64;
        uint32_t so = (uint32_t)(row * 80 + chunk * 16);
        cp_async16(stage_base + so,                 gAh + (size_t)row * K * 2);
        cp_async16(stage_base + 2*ARR_HALF + so,    gAl + (size_t)row * K * 2);
        cp_async16(stage_base + 4*ARR_HALF + so,    gBh + (size_t)row * K * 2);
        cp_async16(stage_base + 6*ARR_HALF + so,    gBl + (size_t)row * K * 2);
    }
}

template<int TERMS, int EPI>
static __device__ __forceinline__ void gemm_body(
    __half* smh, uint32_t smem_base, int tid, int wid,
    const __half* __restrict__ Ahi, const __half* __restrict__ Alo,
    const __half* __restrict__ Bhi, const __half* __restrict__ Blo,
    float* __restrict__ C, int K, int ldc, int bm, int bn)
{
    int wm = (wid >> 2) * 64;   // 2 warp rows of 64
    int wn = (wid & 3) * 32;    // 4 warp cols of 32

    wmma::fragment<wmma::accumulator,16,16,16,float> acc[4][2];
    #pragma unroll
    for (int i = 0; i < 4; i++)
        #pragma unroll
        for (int j = 0; j < 2; j++)
            wmma::fill_fragment(acc[i][j], 0.0f);

    const int NIT = K / KC;

    gemm4_load_stage(smem_base,               tid, Ahi, Alo, Bhi, Blo, bm, bn, K, 0);
    CP_COMMIT();
    gemm4_load_stage(smem_base + STAGE_BYTES, tid, Ahi, Alo, Bhi, Blo, bm, bn, K, KC);
    CP_COMMIT();

    for (int it = 0; it < NIT; it++) {
        CP_WAIT1();
        __syncthreads();

        const __half* st  = smh + (size_t)(it & 1) * STAGE_HALF;
        const __half* sAh = st;
        const __half* sAl = st + ARR_HALF;
        const __half* sBh = st + 2*ARR_HALF;
        const __half* sBl = st + 3*ARR_HALF;

        #pragma unroll
        for (int kk = 0; kk < 2; kk++) {
            wmma::fragment<wmma::matrix_b,16,16,16,__half,wmma::col_major> bh[2], bl[2];
            #pragma unroll
            for (int j = 0; j < 2; j++) {
                wmma::load_matrix_sync(bh[j], sBh + (wn + j*16)*40 + kk*16, 40);
                wmma::load_matrix_sync(bl[j], sBl + (wn + j*16)*40 + kk*16, 40);
            }
            #pragma unroll
            for (int i = 0; i < 4; i++) {
                wmma::fragment<wmma::matrix_a,16,16,16,__half,wmma::row_major> ah, al;
                wmma::load_matrix_sync(ah, sAh + (wm + i*16)*40 + kk*16, 40);
                if (TERMS == 3)
                    wmma::load_matrix_sync(al, sAl + (wm + i*16)*40 + kk*16, 40);
                #pragma unroll
                for (int j = 0; j < 2; j++) {
                    wmma::mma_sync(acc[i][j], ah, bh[j], acc[i][j]);
                    wmma::mma_sync(acc[i][j], ah, bl[j], acc[i][j]);
                    if (TERMS == 3)
                        wmma::mma_sync(acc[i][j], al, bh[j], acc[i][j]);
                }
            }
        }
        __syncthreads();

        int nxt = it + 2;
        if (nxt < NIT)
            gemm4_load_stage(smem_base + (uint32_t)(nxt & 1) * STAGE_BYTES, tid,
                             Ahi, Alo, Bhi, Blo, bm, bn, K, nxt * KC);
        CP_COMMIT();
    }

    if (EPI == 0) {
        #pragma unroll
        for (int i = 0; i < 4; i++)
            #pragma unroll
            for (int j = 0; j < 2; j++) {
                size_t off = (size_t)(bm + wm + i*16) * ldc + bn + wn + j*16;
                wmma::store_matrix_sync(&C[off], acc[i][j], ldc, wmma::mem_row_major);
            }
        return;
    }

    // stage C tile (128 x 128, stride 132) in smem for fused epilogue (67.6KB < 80KB)
    float* sC = (float*)smh;
    #pragma unroll
    for (int i = 0; i < 4; i++)
        #pragma unroll
        for (int j = 0; j < 2; j++)
            wmma::store_matrix_sync(sC + (wm + i*16)*132 + wn + j*16, acc[i][j],
                                    132, wmma::mem_row_major);
    __syncthreads();

    int h = (bn >> 7) & 31;
    if (EPI == 1) {
        bool isk = (bn >= HID);
        __half* Dh = isk ? g_Khi : g_Qhi;
        __half* Dl = isk ? g_Klo : g_Qlo;
        for (int idx = tid; idx < 128*64; idx += 256) {
            int r = idx >> 6, d = idx & 63;
            float x1 = sC[r*132 + d];
            float x2 = sC[r*132 + d + 64];
            int row = bm + r;
            int s   = row & (SEQ-1);
            int b   = row >> 11;
            float c  = g_cos[s*64 + d];
            float sn = g_sin[s*64 + d];
            float o1 = x1*c - x2*sn;
            float o2 = x1*sn + x2*c;
            size_t dst = (((size_t)b * NHEAD + h) * SEQ + s) * HDIM + d;
            __half hi, lo;
            splitf(o1, hi, lo); Dh[dst]    = hi; Dl[dst]    = lo;
            splitf(o2, hi, lo); Dh[dst+64] = hi; Dl[dst+64] = lo;
        }
    } else {
        for (int idx = tid; idx < 128*128; idx += 256) {
            int r = idx >> 7, d = idx & 127;
            int row = bm + r;
            int s   = row & (SEQ-1);
            int b   = row >> 11;
            g_V[(((size_t)b * NHEAD + h) * SEQ + s) * HDIM + d] = __float2half(sC[r*132 + d]);
        }
    }
}

// merged QKV projection: bn < 2*HID -> Q/K (3-term, RoPE epi); else V (2-term)
__global__ void __launch_bounds__(256, 2) gemm_qkv_merged_kernel(
    const __half* __restrict__ Ahi, const __half* __restrict__ Alo,
    const __half* __restrict__ Bhi, const __half* __restrict__ Blo,
    int K, int grid_m, int grid_n)
{
    extern __shared__ __half smh[];
    uint32_t smem_base = smem_u32(smh);
    int tid = threadIdx.x;
    int wid = tid >> 5;

    int pid = blockIdx.x;
    const int GRPW = 16;
    int width = GRPW * grid_n;
    int g   = pid / width;
    int rem = pid - g * width;
    int gm  = grid_m - g * GRPW; if (gm > GRPW) gm = GRPW;
    int bm  = (g * GRPW + (rem % gm)) * 128;
    int bn  = (rem / gm) * 128;

    if (bn < 2*HID)
        gemm_body<3,1>(smh, smem_base, tid, wid, Ahi, Alo, Bhi, Blo,
                       nullptr, K, 0, bm, bn);
    else
        gemm_body<2,2>(smh, smem_base, tid, wid, Ahi, Alo, Bhi, Blo,
                       nullptr, K, 0, bm, bn);
}

// out projection: plain fp32 epilogue
__global__ void __launch_bounds__(256, 2) gemm_out_kernel(
    const __half* __restrict__ Ahi, const __half* __restrict__ Alo,
    const __half* __restrict__ Bhi, const __half* __restrict__ Blo,
    float* __restrict__ C, int K, int ldc, int grid_m, int grid_n)
{
    extern __shared__ __half smh[];
    uint32_t smem_base = smem_u32(smh);
    int tid = threadIdx.x;
    int wid = tid >> 5;

    int pid = blockIdx.x;
    const int GRPW = 16;
    int width = GRPW * grid_n;
    int g   = pid / width;
    int rem = pid - g * width;
    int gm  = grid_m - g * GRPW; if (gm > GRPW) gm = GRPW;
    int bm  = (g * GRPW + (rem % gm)) * 128;
    int bn  = (rem / gm) * 128;

    gemm_body<2,0>(smh, smem_base, tid, wid, Ahi, Alo, Bhi, Blo, C, K, ldc, bm, bn);
}

// ---------------- flash attention, 64-row q tiles, causal, cp.async double buffer ----------------
#define TILE_H   (64*136)
#define TILE_B   (TILE_H*2)
#define FL_SMEM  (8*TILE_B + 64*68*4 + 64*72*2 + 64*132*4 + 3*64*4)

static __device__ __forceinline__ void flash_issue_tile(
    uint32_t dKh, uint32_t dKl, uint32_t dV,
    const __half* __restrict__ Kh, const __half* __restrict__ Kl,
    const __half* __restrict__ V, int tid)
{
    int chunk = tid & 15;
    int r0    = tid >> 4;
    #pragma unroll
    for (int u = 0; u < 4; u++) {
        int r = r0 + u * 16;
        uint32_t so = (uint32_t)(r * 272 + chunk * 16);
        size_t   go = (size_t)r * HDIM * 2 + chunk * 16;
        cp_async16(dKh + so, (const char*)Kh + go);
        cp_async16(dKl + so, (const char*)Kl + go);
        cp_async16(dV  + so, (const char*)V  + go);
    }
}

__global__ void __launch_bounds__(256) flash_kernel() {
    extern __shared__ unsigned char smraw[];
    __half* sQh = (__half*)smraw;
    __half* sQl = sQh + TILE_H;
    __half* sKB = sQl + TILE_H;
    float*  sS  = (float*)(sKB + 6*TILE_H);
    __half* sP  = (__half*)(sS + 64*68);
    float*  sO  = (float*)(sP + 64*72);
    float*  smx = sO + 64*132;
    float*  sl  = smx + 64;

    int tid = threadIdx.x;
    int wid = tid >> 5;
    int qt  = gridDim.x - 1 - blockIdx.x;   // longest CTAs first
    int h   = blockIdx.y;
    int b   = blockIdx.z;
    int bh  = b * NHEAD + h;
    int q0  = qt * 64;

    const float scale = 0.08838834764831845f;

    const __half* Khg = g_Khi + (size_t)bh * SEQ * HDIM;
    const __half* Klg = g_Klo + (size_t)bh * SEQ * HDIM;
    const __half* Vg  = g_V   + (size_t)bh * SEQ * HDIM;

    uint32_t sKB_u = smem_u32(sKB);

    flash_issue_tile(sKB_u, sKB_u + TILE_B, sKB_u + 2*TILE_B, Khg, Klg, Vg, tid);
    CP_COMMIT();

    {
        const __half* Qh = g_Qhi + ((size_t)bh * SEQ + q0) * HDIM;
        const __half* Ql = g_Qlo + ((size_t)bh * SEQ + q0) * HDIM;
        for (int v = tid; v < 1024; v += 256) {
            int r = v >> 4, c = (v & 15) << 3;
            *(int4*)(sQh + r*136 + c) = *(const int4*)(Qh + r*HDIM + c);
            *(int4*)(sQl + r*136 + c) = *(const int4*)(Ql + r*HDIM + c);
        }
    }
    for (int v = tid; v < 64*132; v += 256) sO[v] = 0.0f;
    if (tid < 64) { smx[tid] = -INFINITY; sl[tid] = 0.0f; }

    int wm = (wid >> 1) * 16;

    for (int kt = 0; kt <= qt; kt++) {
        if (kt + 1 <= qt) {
            uint32_t nb = sKB_u + (uint32_t)((kt + 1) & 1) * 3 * TILE_B;
            flash_issue_tile(nb, nb + TILE_B, nb + 2*TILE_B,
                             Khg + (size_t)(kt+1)*64*HDIM,
                             Klg + (size_t)(kt+1)*64*HDIM,
                             Vg  + (size_t)(kt+1)*64*HDIM, tid);
        }
        CP_COMMIT();
        CP_WAIT1();
        __syncthreads();

        __half* sKh = sKB + (size_t)(kt & 1) * 3 * TILE_H;
        __half* sKl = sKh + TILE_H;
        __half* sV  = sKh + 2*TILE_H;

        // S = Q K^T (3-term split)
        {
            int wn = (wid & 1) * 32;
            wmma::fragment<wmma::accumulator,16,16,16,float> sacc[2];
            wmma::fill_fragment(sacc[0], 0.0f);
            wmma::fill_fragment(sacc[1], 0.0f);
            #pragma unroll
            for (int d8 = 0; d8 < 8; d8++) {
                wmma::fragment<wmma::matrix_a,16,16,16,__half,wmma::row_major> ah, al;
                wmma::load_matrix_sync(ah, sQh + wm*136 + d8*16, 136);
                wmma::load_matrix_sync(al, sQl + wm*136 + d8*16, 136);
                #pragma unroll
                for (int j = 0; j < 2; j++) {
                    wmma::fragment<wmma::matrix_b,16,16,16,__half,wmma::col_major> kh, kl;
                    wmma::load_matrix_sync(kh, sKh + (wn + j*16)*136 + d8*16, 136);
                    wmma::load_matrix_sync(kl, sKl + (wn + j*16)*136 + d8*16, 136);
                    wmma::mma_sync(sacc[j], ah, kh, sacc[j]);
                    wmma::mma_sync(sacc[j], ah, kl, sacc[j]);
                    wmma::mma_sync(sacc[j], al, kh, sacc[j]);
                }
            }
            wmma::store_matrix_sync(sS + wm*68 + wn,      sacc[0], 68, wmma::mem_row_major);
            wmma::store_matrix_sync(sS + wm*68 + wn + 16, sacc[1], 68, wmma::mem_row_major);
        }
        __syncthreads();

        // online softmax + fused O rescale (4 threads per row)
        {
            int r    = tid >> 2;
            int lane = tid & 3;
            bool diag = (kt == qt);
            int jmax = diag ? (r + 1) : 64;

            float lm = -INFINITY;
            #pragma unroll
            for (int jj = 0; jj < 16; jj++) {
                int j = lane*16 + jj;
                if (j < jmax) lm = fmaxf(lm, sS[r*68 + j] * scale);
            }
            lm = fmaxf(lm, __shfl_xor_sync(0xffffffffu, lm, 1));
            lm = fmaxf(lm, __shfl_xor_sync(0xffffffffu, lm, 2));
            float mo = smx[r];
            float mn = fmaxf(mo, lm);

            float rl = 0.0f;
            #pragma unroll
            for (int jj = 0; jj < 16; jj++) {
                int j = lane*16 + jj;
                float p = 0.0f;
                if (j < jmax) { p = __expf(sS[r*68 + j] * scale - mn); rl += p; }
                sP[r*72 + j] = __float2half(p);
            }
            rl += __shfl_xor_sync(0xffffffffu, rl, 1);
            rl += __shfl_xor_sync(0xffffffffu, rl, 2);

            float a = __expf(mo - mn);
            if (lane == 0) {
                smx[r] = mn;
                sl[r]  = sl[r] * a + rl;
            }
            #pragma unroll
            for (int dd = 0; dd < 32; dd++)
                sO[r*132 + lane*32 + dd] *= a;
        }
        __syncthreads();

        // O += P @ V
        {
            int wn2 = (wid & 1) * 64;
            wmma::fragment<wmma::accumulator,16,16,16,float> oc[4];
            #pragma unroll
            for (int j = 0; j < 4; j++)
                wmma::load_matrix_sync(oc[j], sO + wm*132 + wn2 + j*16, 132, wmma::mem_row_major);
            #pragma unroll
            for (int kk = 0; kk < 4; kk++) {
                wmma::fragment<wmma::matrix_a,16,16,16,__half,wmma::row_major> pf;
                wmma::load_matrix_sync(pf, sP + wm*72 + kk*16, 72);
                #pragma unroll
                for (int j = 0; j < 4; j++) {
                    wmma::fragment<wmma::matrix_b,16,16,16,__half,wmma::row_major> vf;
                    wmma::load_matrix_sync(vf, sV + (kk*16)*136 + wn2 + j*16, 136);
                    wmma::mma_sync(oc[j], pf, vf, oc[j]);
                }
            }
            #pragma unroll
            for (int j = 0; j < 4; j++)
                wmma::store_matrix_sync(sO + wm*132 + wn2 + j*16, oc[j], 132, wmma::mem_row_major);
        }
        __syncthreads();
    }

    for (int v = tid; v < 64*128; v += 256) {
        int r = v >> 7, d = v & 127;
        float o = sO[r*132 + d] / sl[r];
        size_t dst = ((size_t)b * SEQ + q0 + r) * HID + (size_t)h * HDIM + d;
        __half hi, lo; splitf(o, hi, lo);
        g_AOhi[dst] = hi; g_AOlo[dst] = lo;
    }
}

// ---------------- launch ----------------
extern "C" void kernel_launch(void* const* d_in, const int* in_sizes, int n_in,
                              void* d_out, int out_size) {
    const float* X    = (const float*)d_in[0];
    const float* Wqkv = (const float*)d_in[1];
    const float* Wo   = (const float*)d_in[2];

    cudaFuncSetAttribute(flash_kernel, cudaFuncAttributeMaxDynamicSharedMemorySize, FL_SMEM);
    cudaFuncSetAttribute(gemm_qkv_merged_kernel, cudaFuncAttributeMaxDynamicSharedMemorySize, GEMM_SMEM);
    cudaFuncSetAttribute(gemm_out_kernel, cudaFuncAttributeMaxDynamicSharedMemorySize, GEMM_SMEM);

    __half *Xhi, *Xlo, *Wqh, *Wql, *Woh, *Wol, *AOh, *AOl;
    cudaGetSymbolAddress((void**)&Xhi, g_Xhi);
    cudaGetSymbolAddress((void**)&Xlo, g_Xlo);
    cudaGetSymbolAddress((void**)&Wqh, g_Wqkvhi);
    cudaGetSymbolAddress((void**)&Wql, g_Wqkvlo);
    cudaGetSymbolAddress((void**)&Woh, g_Wohi);
    cudaGetSymbolAddress((void**)&Wol, g_Wolo);
    cudaGetSymbolAddress((void**)&AOh, g_AOhi);
    cudaGetSymbolAddress((void**)&AOl, g_AOlo);

    split_x_kernel   <<<(MROWS*HID + 255)/256, 256>>>(X);
    split_wqkv_kernel<<<(QKVN*HID  + 255)/256, 256>>>(Wqkv);
    split_wo_kernel  <<<(HID*HID   + 255)/256, 256>>>(Wo);
    rope_table_kernel<<<(SEQ*64    + 255)/256, 256>>>();

    // full QKV projection in one launch (M=4096, N=12288), 128x128 tiles
    gemm_qkv_merged_kernel<<<(MROWS/128)*(QKVN/128), 256, GEMM_SMEM>>>(
        Xhi, Xlo, Wqh, Wql, HID, MROWS/128, QKVN/128);

    flash_kernel<<<dim3(SEQ/64, NHEAD, BATCH), 256, FL_SMEM>>>();

    // Output projection (N=4096): 2-term, direct fp32 store
    gemm_out_kernel<<<(MROWS/128)*(HID/128), 256, GEMM_SMEM>>>(
        AOh, AOl, Woh, Wol, (float*)d_out, HID, HID, MROWS/128, HID/128);
}

// round 8
// speedup vs baseline: 1.0038x; 1.0038x over previous
#include <cuda_runtime.h>
#include <cuda_fp16.h>
#include <mma.h>
#include <math.h>
#include <stdint.h>

using namespace nvcuda;

#define BATCH 2
#define SEQ   2048
#define HID   4096
#define NHEAD 32
#define HDIM  128
#define MROWS (BATCH*SEQ)     /* 4096 */
#define QKVN  (3*HID)         /* 12288 */

// ---------------- scratch ----------------
__device__ __half g_Xhi   [MROWS*HID];
__device__ __half g_Xlo   [MROWS*HID];
__device__ __half g_Wqkvhi[QKVN*HID];
__device__ __half g_Wqkvlo[QKVN*HID];
__device__ __half g_Wohi  [HID*HID];
__device__ __half g_Wolo  [HID*HID];
__device__ __half g_Qhi   [MROWS*HID];
__device__ __half g_Qlo   [MROWS*HID];
__device__ __half g_Khi   [MROWS*HID];
__device__ __half g_Klo   [MROWS*HID];
__device__ __half g_V     [MROWS*HID];
__device__ __half g_AOhi  [MROWS*HID];
__device__ __half g_AOlo  [MROWS*HID];
__device__ float  g_cos   [SEQ*64];
__device__ float  g_sin   [SEQ*64];

__device__ __forceinline__ void splitf(float x, __half &hi, __half &lo) {
    hi = __float2half(x);
    lo = __float2half(x - __half2float(hi));
}

// ---------------- cp.async helpers ----------------
static __device__ __forceinline__ uint32_t smem_u32(const void* p) {
    uint32_t a;
    asm("{ .reg .u64 t; cvta.to.shared.u64 t, %1; cvt.u32.u64 %0, t; }" : "=r"(a) : "l"(p));
    return a;
}
static __device__ __forceinline__ void cp_async16(uint32_t dst, const void* src) {
    asm volatile("cp.async.cg.shared.global [%0], [%1], 16;\n" :: "r"(dst), "l"(src));
}
#define CP_COMMIT() asm volatile("cp.async.commit_group;\n" ::: "memory")
#define CP_WAIT1()  asm volatile("cp.async.wait_group 1;\n" ::: "memory")

// ---------------- elementwise split kernels ----------------
__device__ __forceinline__ void split_body(const float* __restrict__ src,
                                           __half* __restrict__ hi,
                                           __half* __restrict__ lo, int n) {
    int idx = blockIdx.x * blockDim.x + threadIdx.x;
    if (idx < n) {
        float x = src[idx];
        __half h, l; splitf(x, h, l);
        hi[idx] = h; lo[idx] = l;
    }
}
__global__ void __launch_bounds__(256) split_x_kernel(const float* __restrict__ src) {
    split_body(src, g_Xhi, g_Xlo, MROWS*HID);
}
__global__ void __launch_bounds__(256) split_wqkv_kernel(const float* __restrict__ src) {
    split_body(src, g_Wqkvhi, g_Wqkvlo, QKVN*HID);
}
__global__ void __launch_bounds__(256) split_wo_kernel(const float* __restrict__ src) {
    split_body(src, g_Wohi, g_Wolo, HID*HID);
}

// ---------------- RoPE cos/sin table ----------------
__global__ void __launch_bounds__(256) rope_table_kernel() {
    int idx = blockIdx.x * blockDim.x + threadIdx.x;
    if (idx >= SEQ*64) return;
    int i = idx & 63;
    int s = idx >> 6;
    double inv = pow(10000.0, -((double)(2*i)) / 128.0);
    float invf = (float)inv;
    float ang  = (float)s * invf;
    g_cos[idx] = (float)cos((double)ang);
    g_sin[idx] = (float)sin((double)ang);
}

// =====================================================================
//  Pipelined split-fp16 GEMM: CTA 128x128, 256 threads, warp 64x32.
//  KC=32, 2-stage cp.async, 2 CTAs/SM (cross-CTA bubble hiding).
//  TERMS: 3 or 2 split terms.
//  EPI: 0 = fp32 C direct ; 1 = fused RoPE+transpose+split (Q/K) ;
//       2 = direct fp16 V transpose.
// =====================================================================

#define KC        32
#define ARR_HALF  (128*40)                 /* 32 data halves + 8 pad */
#define STAGE_HALF (4*ARR_HALF)            /* 20480 */
#define STAGE_BYTES (STAGE_HALF*2)         /* 40960 */
#define GEMM_SMEM (2*STAGE_BYTES)          /* 81920 -> 2 CTAs/SM */

static __device__ __forceinline__ void gemm4_load_stage(
    uint32_t stage_base, int tid,
    const __half* __restrict__ Ahi, const __half* __restrict__ Alo,
    const __half* __restrict__ Bhi, const __half* __restrict__ Blo,
    int bm, int bn, int K, int k0)
{
    int chunk = tid & 3;        // 16B chunk within 64B data row
    int r0    = tid >> 2;       // 0..63
    const char* gAh = (const char*)(Ahi + (size_t)bm * K + k0) + chunk * 16;
    const char* gAl = (const char*)(Alo + (size_t)bm * K + k0) + chunk * 16;
    const char* gBh = (const char*)(Bhi + (size_t)bn * K + k0) + chunk * 16;
    const char* gBl = (const char*)(Blo + (size_t)bn * K + k0) + chunk * 16;
    #pragma unroll
    for (int u = 0; u < 2; u++) {
        int row = r0 + u * 64;
        uint32_t so = (uint32_t)(row * 80 + chunk * 16);
        cp_async16(stage_base + so,                 gAh + (size_t)row * K * 2);
        cp_async16(stage_base + 2*ARR_HALF + so,    gAl + (size_t)row * K * 2);
        cp_async16(stage_base + 4*ARR_HALF + so,    gBh + (size_t)row * K * 2);
        cp_async16(stage_base + 6*ARR_HALF + so,    gBl + (size_t)row * K * 2);
    }
}

template<int TERMS, int EPI>
static __device__ __forceinline__ void gemm_body(
    __half* smh, uint32_t smem_base, int tid, int wid,
    const __half* __restrict__ Ahi, const __half* __restrict__ Alo,
    const __half* __restrict__ Bhi, const __half* __restrict__ Blo,
    float* __restrict__ C, int K, int ldc, int bm, int bn)
{
    int wm = (wid >> 2) * 64;   // 2 warp rows of 64
    int wn = (wid & 3) * 32;    // 4 warp cols of 32

    wmma::fragment<wmma::accumulator,16,16,16,float> acc[4][2];
    #pragma unroll
    for (int i = 0; i < 4; i++)
        #pragma unroll
        for (int j = 0; j < 2; j++)
            wmma::fill_fragment(acc[i][j], 0.0f);

    const int NIT = K / KC;

    gemm4_load_stage(smem_base,               tid, Ahi, Alo, Bhi, Blo, bm, bn, K, 0);
    CP_COMMIT();
    gemm4_load_stage(smem_base + STAGE_BYTES, tid, Ahi, Alo, Bhi, Blo, bm, bn, K, KC);
    CP_COMMIT();

    for (int it = 0; it < NIT; it++) {
        CP_WAIT1();
        __syncthreads();

        const __half* st  = smh + (size_t)(it & 1) * STAGE_HALF;
        const __half* sAh = st;
        const __half* sAl = st + ARR_HALF;
        const __half* sBh = st + 2*ARR_HALF;
        const __half* sBl = st + 3*ARR_HALF;

        #pragma unroll
        for (int kk = 0; kk < 2; kk++) {
            wmma::fragment<wmma::matrix_b,16,16,16,__half,wmma::col_major> bh[2], bl[2];
            #pragma unroll
            for (int j = 0; j < 2; j++) {
                wmma::load_matrix_sync(bh[j], sBh + (wn + j*16)*40 + kk*16, 40);
                wmma::load_matrix_sync(bl[j], sBl + (wn + j*16)*40 + kk*16, 40);
            }
            #pragma unroll
            for (int i = 0; i < 4; i++) {
                wmma::fragment<wmma::matrix_a,16,16,16,__half,wmma::row_major> ah, al;
                wmma::load_matrix_sync(ah, sAh + (wm + i*16)*40 + kk*16, 40);
                if (TERMS == 3)
                    wmma::load_matrix_sync(al, sAl + (wm + i*16)*40 + kk*16, 40);
                #pragma unroll
                for (int j = 0; j < 2; j++) {
                    wmma::mma_sync(acc[i][j], ah, bh[j], acc[i][j]);
                    wmma::mma_sync(acc[i][j], ah, bl[j], acc[i][j]);
                    if (TERMS == 3)
                        wmma::mma_sync(acc[i][j], al, bh[j], acc[i][j]);
                }
            }
        }
        __syncthreads();

        int nxt = it + 2;
        if (nxt < NIT)
            gemm4_load_stage(smem_base + (uint32_t)(nxt & 1) * STAGE_BYTES, tid,
                             Ahi, Alo, Bhi, Blo, bm, bn, K, nxt * KC);
        CP_COMMIT();
    }

    if (EPI == 0) {
        #pragma unroll
        for (int i = 0; i < 4; i++)
            #pragma unroll
            for (int j = 0; j < 2; j++) {
                size_t off = (size_t)(bm + wm + i*16) * ldc + bn + wn + j*16;
                wmma::store_matrix_sync(&C[off], acc[i][j], ldc, wmma::mem_row_major);
            }
        return;
    }

    // stage C tile (128 x 128, stride 132) in smem for fused epilogue (67.6KB < 80KB)
    float* sC = (float*)smh;
    #pragma unroll
    for (int i = 0; i < 4; i++)
        #pragma unroll
        for (int j = 0; j < 2; j++)
            wmma::store_matrix_sync(sC + (wm + i*16)*132 + wn + j*16, acc[i][j],
                                    132, wmma::mem_row_major);
    __syncthreads();

    int h = (bn >> 7) & 31;
    if (EPI == 1) {
        bool isk = (bn >= HID);
        __half* Dh = isk ? g_Khi : g_Qhi;
        __half* Dl = isk ? g_Klo : g_Qlo;
        for (int idx = tid; idx < 128*64; idx += 256) {
            int r = idx >> 6, d = idx & 63;
            float x1 = sC[r*132 + d];
            float x2 = sC[r*132 + d + 64];
            int row = bm + r;
            int s   = row & (SEQ-1);
            int b   = row >> 11;
            float c  = g_cos[s*64 + d];
            float sn = g_sin[s*64 + d];
            float o1 = x1*c - x2*sn;
            float o2 = x1*sn + x2*c;
            size_t dst = (((size_t)b * NHEAD + h) * SEQ + s) * HDIM + d;
            __half hi, lo;
            splitf(o1, hi, lo); Dh[dst]    = hi; Dl[dst]    = lo;
            splitf(o2, hi, lo); Dh[dst+64] = hi; Dl[dst+64] = lo;
        }
    } else {
        for (int idx = tid; idx < 128*128; idx += 256) {
            int r = idx >> 7, d = idx & 127;
            int row = bm + r;
            int s   = row & (SEQ-1);
            int b   = row >> 11;
            g_V[(((size_t)b * NHEAD + h) * SEQ + s) * HDIM + d] = __float2half(sC[r*132 + d]);
        }
    }
}

// merged QKV projection: bn < 2*HID -> Q/K (3-term, RoPE epi); else V (2-term)
__global__ void __launch_bounds__(256, 2) gemm_qkv_merged_kernel(
    const __half* __restrict__ Ahi, const __half* __restrict__ Alo,
    const __half* __restrict__ Bhi, const __half* __restrict__ Blo,
    int K, int grid_m, int grid_n)
{
    extern __shared__ __half smh[];
    uint32_t smem_base = smem_u32(smh);
    int tid = threadIdx.x;
    int wid = tid >> 5;

    int pid = blockIdx.x;
    const int GRPW = 16;
    int width = GRPW * grid_n;
    int g   = pid / width;
    int rem = pid - g * width;
    int gm  = grid_m - g * GRPW; if (gm > GRPW) gm = GRPW;
    int bm  = (g * GRPW + (rem % gm)) * 128;
    int bn  = (rem / gm) * 128;

    if (bn < 2*HID)
        gemm_body<3,1>(smh, smem_base, tid, wid, Ahi, Alo, Bhi, Blo,
                       nullptr, K, 0, bm, bn);
    else
        gemm_body<2,2>(smh, smem_base, tid, wid, Ahi, Alo, Bhi, Blo,
                       nullptr, K, 0, bm, bn);
}

// out projection: plain fp32 epilogue
__global__ void __launch_bounds__(256, 2) gemm_out_kernel(
    const __half* __restrict__ Ahi, const __half* __restrict__ Alo,
    const __half* __restrict__ Bhi, const __half* __restrict__ Blo,
    float* __restrict__ C, int K, int ldc, int grid_m, int grid_n)
{
    extern __shared__ __half smh[];
    uint32_t smem_base = smem_u32(smh);
    int tid = threadIdx.x;
    int wid = tid >> 5;

    int pid = blockIdx.x;
    const int GRPW = 16;
    int width = GRPW * grid_n;
    int g   = pid / width;
    int rem = pid - g * width;
    int gm  = grid_m - g * GRPW; if (gm > GRPW) gm = GRPW;
    int bm  = (g * GRPW + (rem % gm)) * 128;
    int bn  = (rem / gm) * 128;

    gemm_body<2,0>(smh, smem_base, tid, wid, Ahi, Alo, Bhi, Blo, C, K, ldc, bm, bn);
}

// ---------------- flash attention, 64-row q tiles, causal, cp.async double buffer ----------------
#define TILE_H   (64*136)
#define TILE_B   (TILE_H*2)
#define FL_SMEM  (8*TILE_B + 64*68*4 + 64*72*2 + 64*132*4 + 3*64*4)

static __device__ __forceinline__ void flash_issue_tile(
    uint32_t dKh, uint32_t dKl, uint32_t dV,
    const __half* __restrict__ Kh, const __half* __restrict__ Kl,
    const __half* __restrict__ V, int tid)
{
    int chunk = tid & 15;
    int r0    = tid >> 4;
    #pragma unroll
    for (int u = 0; u < 4; u++) {
        int r = r0 + u * 16;
        uint32_t so = (uint32_t)(r * 272 + chunk * 16);
        size_t   go = (size_t)r * HDIM * 2 + chunk * 16;
        cp_async16(dKh + so, (const char*)Kh + go);
        cp_async16(dKl + so, (const char*)Kl + go);
        cp_async16(dV  + so, (const char*)V  + go);
    }
}

__global__ void __launch_bounds__(256) flash_kernel() {
    extern __shared__ unsigned char smraw[];
    __half* sQh = (__half*)smraw;
    __half* sQl = sQh + TILE_H;
    __half* sKB = sQl + TILE_H;
    float*  sS  = (float*)(sKB + 6*TILE_H);
    __half* sP  = (__half*)(sS + 64*68);
    float*  sO  = (float*)(sP + 64*72);
    float*  smx = sO + 64*132;
    float*  sl  = smx + 64;

    int tid = threadIdx.x;
    int wid = tid >> 5;
    int qt  = gridDim.x - 1 - blockIdx.x;   // longest CTAs first
    int h   = blockIdx.y;
    int b   = blockIdx.z;
    int bh  = b * NHEAD + h;
    int q0  = qt * 64;

    const float scale = 0.08838834764831845f;

    const __half* Khg = g_Khi + (size_t)bh * SEQ * HDIM;
    const __half* Klg = g_Klo + (size_t)bh * SEQ * HDIM;
    const __half* Vg  = g_V   + (size_t)bh * SEQ * HDIM;

    uint32_t sKB_u = smem_u32(sKB);

    flash_issue_tile(sKB_u, sKB_u + TILE_B, sKB_u + 2*TILE_B, Khg, Klg, Vg, tid);
    CP_COMMIT();

    {
        const __half* Qh = g_Qhi + ((size_t)bh * SEQ + q0) * HDIM;
        const __half* Ql = g_Qlo + ((size_t)bh * SEQ + q0) * HDIM;
        for (int v = tid; v < 1024; v += 256) {
            int r = v >> 4, c = (v & 15) << 3;
            *(int4*)(sQh + r*136 + c) = *(const int4*)(Qh + r*HDIM + c);
            *(int4*)(sQl + r*136 + c) = *(const int4*)(Ql + r*HDIM + c);
        }
    }
    for (int v = tid; v < 64*132; v += 256) sO[v] = 0.0f;
    if (tid < 64) { smx[tid] = -INFINITY; sl[tid] = 0.0f; }

    int wm = (wid >> 1) * 16;

    for (int kt = 0; kt <= qt; kt++) {
        if (kt + 1 <= qt) {
            uint32_t nb = sKB_u + (uint32_t)((kt + 1) & 1) * 3 * TILE_B;
            flash_issue_tile(nb, nb + TILE_B, nb + 2*TILE_B,
                             Khg + (size_t)(kt+1)*64*HDIM,
                             Klg + (size_t)(kt+1)*64*HDIM,
                             Vg  + (size_t)(kt+1)*64*HDIM, tid);
        }
        CP_COMMIT();
        CP_WAIT1();
        __syncthreads();

        __half* sKh = sKB + (size_t)(kt & 1) * 3 * TILE_H;
        __half* sKl = sKh + TILE_H;
        __half* sV  = sKh + 2*TILE_H;

        // S = Q K^T (3-term split)
        {
            int wn = (wid & 1) * 32;
            wmma::fragment<wmma::accumulator,16,16,16,float> sacc[2];
            wmma::fill_fragment(sacc[0], 0.0f);
            wmma::fill_fragment(sacc[1], 0.0f);
            #pragma unroll
            for (int d8 = 0; d8 < 8; d8++) {
                wmma::fragment<wmma::matrix_a,16,16,16,__half,wmma::row_major> ah, al;
                wmma::load_matrix_sync(ah, sQh + wm*136 + d8*16, 136);
                wmma::load_matrix_sync(al, sQl + wm*136 + d8*16, 136);
                #pragma unroll
                for (int j = 0; j < 2; j++) {
                    wmma::fragment<wmma::matrix_b,16,16,16,__half,wmma::col_major> kh, kl;
                    wmma::load_matrix_sync(kh, sKh + (wn + j*16)*136 + d8*16, 136);
                    wmma::load_matrix_sync(kl, sKl + (wn + j*16)*136 + d8*16, 136);
                    wmma::mma_sync(sacc[j], ah, kh, sacc[j]);
                    wmma::mma_sync(sacc[j], ah, kl, sacc[j]);
                    wmma::mma_sync(sacc[j], al, kh, sacc[j]);
                }
            }
            wmma::store_matrix_sync(sS + wm*68 + wn,      sacc[0], 68, wmma::mem_row_major);
            wmma::store_matrix_sync(sS + wm*68 + wn + 16, sacc[1], 68, wmma::mem_row_major);
        }
        __syncthreads();

        // online softmax + fused O rescale (4 threads per row)
        {
            int r    = tid >> 2;
            int lane = tid & 3;
            bool diag = (kt == qt);
            int jmax = diag ? (r + 1) : 64;

            float lm = -INFINITY;
            #pragma unroll
            for (int jj = 0; jj < 16; jj++) {
                int j = lane*16 + jj;
                if (j < jmax) lm = fmaxf(lm, sS[r*68 + j] * scale);
            }
            lm = fmaxf(lm, __shfl_xor_sync(0xffffffffu, lm, 1));
            lm = fmaxf(lm, __shfl_xor_sync(0xffffffffu, lm, 2));
            float mo = smx[r];
            float mn = fmaxf(mo, lm);

            float rl = 0.0f;
            #pragma unroll
            for (int jj = 0; jj < 16; jj++) {
                int j = lane*16 + jj;
                float p = 0.0f;
                if (j < jmax) { p = __expf(sS[r*68 + j] * scale - mn); rl += p; }
                sP[r*72 + j] = __float2half(p);
            }
            rl += __shfl_xor_sync(0xffffffffu, rl, 1);
            rl += __shfl_xor_sync(0xffffffffu, rl, 2);

            float a = __expf(mo - mn);
            if (lane == 0) {
                smx[r] = mn;
                sl[r]  = sl[r] * a + rl;
            }
            #pragma unroll
            for (int dd = 0; dd < 32; dd++)
                sO[r*132 + lane*32 + dd] *= a;
        }
        __syncthreads();

        // O += P @ V
        {
            int wn2 = (wid & 1) * 64;
            wmma::fragment<wmma::accumulator,16,16,16,float> oc[4];
            #pragma unroll
            for (int j = 0; j < 4; j++)
                wmma::load_matrix_sync(oc[j], sO + wm*132 + wn2 + j*16, 132, wmma::mem_row_major);
            #pragma unroll
            for (int kk = 0; kk < 4; kk++) {
                wmma::fragment<wmma::matrix_a,16,16,16,__half,wmma::row_major> pf;
                wmma::load_matrix_sync(pf, sP + wm*72 + kk*16, 72);
                #pragma unroll
                for (int j = 0; j < 4; j++) {
                    wmma::fragment<wmma::matrix_b,16,16,16,__half,wmma::row_major> vf;
                    wmma::load_matrix_sync(vf, sV + (kk*16)*136 + wn2 + j*16, 136);
                    wmma::mma_sync(oc[j], pf, vf, oc[j]);
                }
            }
            #pragma unroll
            for (int j = 0; j < 4; j++)
                wmma::store_matrix_sync(sO + wm*132 + wn2 + j*16, oc[j], 132, wmma::mem_row_major);
        }
        __syncthreads();
    }

    for (int v = tid; v < 64*128; v += 256) {
        int r = v >> 7, d = v & 127;
        float o = sO[r*132 + d] / sl[r];
        size_t dst = ((size_t)b * SEQ + q0 + r) * HID + (size_t)h * HDIM + d;
        __half hi, lo; splitf(o, hi, lo);
        g_AOhi[dst] = hi; g_AOlo[dst] = lo;
    }
}

// ---------------- launch ----------------
extern "C" void kernel_launch(void* const* d_in, const int* in_sizes, int n_in,
                              void* d_out, int out_size) {
    const float* X    = (const float*)d_in[0];
    const float* Wqkv = (const float*)d_in[1];
    const float* Wo   = (const float*)d_in[2];

    cudaFuncSetAttribute(flash_kernel, cudaFuncAttributeMaxDynamicSharedMemorySize, FL_SMEM);
    cudaFuncSetAttribute(gemm_qkv_merged_kernel, cudaFuncAttributeMaxDynamicSharedMemorySize, GEMM_SMEM);
    cudaFuncSetAttribute(gemm_out_kernel, cudaFuncAttributeMaxDynamicSharedMemorySize, GEMM_SMEM);

    __half *Xhi, *Xlo, *Wqh, *Wql, *Woh, *Wol, *AOh, *AOl;
    cudaGetSymbolAddress((void**)&Xhi, g_Xhi);
    cudaGetSymbolAddress((void**)&Xlo, g_Xlo);
    cudaGetSymbolAddress((void**)&Wqh, g_Wqkvhi);
    cudaGetSymbolAddress((void**)&Wql, g_Wqkvlo);
    cudaGetSymbolAddress((void**)&Woh, g_Wohi);
    cudaGetSymbolAddress((void**)&Wol, g_Wolo);
    cudaGetSymbolAddress((void**)&AOh, g_AOhi);
    cudaGetSymbolAddress((void**)&AOl, g_AOlo);

    split_x_kernel   <<<(MROWS*HID + 255)/256, 256>>>(X);
    split_wqkv_kernel<<<(QKVN*HID  + 255)/256, 256>>>(Wqkv);
    split_wo_kernel  <<<(HID*HID   + 255)/256, 256>>>(Wo);
    rope_table_kernel<<<(SEQ*64    + 255)/256, 256>>>();

    // full QKV projection in one launch (M=4096, N=12288), 128x128 tiles
    gemm_qkv_merged_kernel<<<(MROWS/128)*(QKVN/128), 256, GEMM_SMEM>>>(
        Xhi, Xlo, Wqh, Wql, HID, MROWS/128, QKVN/128);

    flash_kernel<<<dim3(SEQ/64, NHEAD, BATCH), 256, FL_SMEM>>>();

    // Output projection (N=4096): 2-term, direct fp32 store
    gemm_out_kernel<<<(MROWS/128)*(HID/128), 256, GEMM_SMEM>>>(
        AOh, AOl, Woh, Wol, (float*)d_out, HID, HID, MROWS/128, HID/128);
}